// round 1
// baseline (speedup 1.0000x reference)
#include <cuda_runtime.h>
#include <math.h>

#define RR 262144   // B*N
#define NN 65536
#define CC 192
#define HH 6
#define DD 32

// Scratch (device globals: no allocation in kernel_launch)
__device__ float g_qkv[RR * 576];   // ~604 MB
__device__ float g_ret[RR * CC];    // ~201 MB
__device__ float g_h[RR * CC];      // ~201 MB
__device__ float g_kv[4 * HH * DD * DD];  // [b][h][d][e]

__device__ __forceinline__ float warp_sum(float v) {
    v += __shfl_xor_sync(0xffffffffu, v, 16);
    v += __shfl_xor_sync(0xffffffffu, v, 8);
    v += __shfl_xor_sync(0xffffffffu, v, 4);
    v += __shfl_xor_sync(0xffffffffu, v, 2);
    v += __shfl_xor_sync(0xffffffffu, v, 1);
    return v;
}

// Generic K=192 GEMM: OUT[r][c0+c] = epi( sum_k A[r][k] * W[c0+c][k] + bias[c0+c] )
// Tile: 64 rows x 96 cols, 256 threads, each thread 4x6 micro-tile.
// EPI: 0 = none, 1 = exact gelu, 2 = +resid
// ASEL: 0 = Aext, 1 = g_ret, 2 = g_h ; OSEL: 0 = Oext, 1 = g_qkv, 2 = g_h
template<int EPI, int ASEL, int OSEL>
__global__ __launch_bounds__(256) void gemm192(
    const float* __restrict__ Aext, const float* __restrict__ W,
    const float* __restrict__ bias, float* __restrict__ Oext,
    const float* __restrict__ resid, int ncols)
{
    const float* A = (ASEL == 0) ? Aext : (ASEL == 1 ? g_ret : g_h);
    float* OUT = (OSEL == 0) ? Oext : (OSEL == 1 ? g_qkv : g_h);

    __shared__ float xs[64][68];   // [row][k]  (pad 68 -> 16B-aligned rows)
    __shared__ float ws[64][98];   // [k][col]  (pad 98 -> 8B-aligned, few conflicts)

    int row0 = blockIdx.x * 64;
    int c0 = blockIdx.y * 96;
    int tid = threadIdx.x;
    int ty = tid >> 4, tx = tid & 15;

    float acc[4][6];
#pragma unroll
    for (int i = 0; i < 4; i++)
#pragma unroll
        for (int j = 0; j < 6; j++) acc[i][j] = 0.f;

    for (int kt = 0; kt < 192; kt += 64) {
        // Load A tile [64 x 64] as float4 rows (coalesced)
        for (int i = tid; i < 1024; i += 256) {
            int r = i >> 4, k4 = i & 15;
            float4 v = *(const float4*)(A + (size_t)(row0 + r) * 192 + kt + k4 * 4);
            *(float4*)&xs[r][k4 * 4] = v;
        }
        // Load W tile [96 x 64], transpose into [k][c]
        for (int i = tid; i < 1536; i += 256) {
            int c = i >> 4, k4 = i & 15;
            float4 v = *(const float4*)(W + (size_t)(c0 + c) * 192 + kt + k4 * 4);
            ws[k4 * 4 + 0][c] = v.x;
            ws[k4 * 4 + 1][c] = v.y;
            ws[k4 * 4 + 2][c] = v.z;
            ws[k4 * 4 + 3][c] = v.w;
        }
        __syncthreads();

#pragma unroll 8
        for (int k = 0; k < 64; k++) {
            float aa[4];
            aa[0] = xs[ty * 4 + 0][k];
            aa[1] = xs[ty * 4 + 1][k];
            aa[2] = xs[ty * 4 + 2][k];
            aa[3] = xs[ty * 4 + 3][k];
            float2 b01 = *(const float2*)&ws[k][tx * 6];
            float2 b23 = *(const float2*)&ws[k][tx * 6 + 2];
            float2 b45 = *(const float2*)&ws[k][tx * 6 + 4];
            float bb[6] = {b01.x, b01.y, b23.x, b23.y, b45.x, b45.y};
#pragma unroll
            for (int i = 0; i < 4; i++)
#pragma unroll
                for (int j = 0; j < 6; j++)
                    acc[i][j] = fmaf(aa[i], bb[j], acc[i][j]);
        }
        __syncthreads();
    }

#pragma unroll
    for (int i = 0; i < 4; i++) {
        int r = row0 + ty * 4 + i;
#pragma unroll
        for (int j = 0; j < 6; j++) {
            int c = c0 + tx * 6 + j;
            float v = acc[i][j] + bias[c];
            if (EPI == 1) v = 0.5f * v * (1.0f + erff(v * 0.70710678118654752440f));
            if (EPI == 2) v += resid[(size_t)r * ncols + c];
            OUT[(size_t)r * ncols + c] = v;
        }
    }
}

__global__ void zero_kv_kernel() {
    int i = blockIdx.x * blockDim.x + threadIdx.x;
    if (i < 4 * HH * DD * DD) g_kv[i] = 0.f;
}

// LayerNorm(k), LayerNorm(v) then kv[b,h,d,e] += ln_k[d]*ln_v[e], summed over n, /N.
// grid (32 chunks, 24 b*h), 256 threads = 8 warps, warp-per-row (lane = channel dim)
__global__ __launch_bounds__(256) void ln_kv_kernel(
    const float* __restrict__ klnw, const float* __restrict__ klnb,
    const float* __restrict__ vlnw, const float* __restrict__ vlnb)
{
    int bh = blockIdx.y;
    int b = bh / HH, h = bh - b * HH;
    int lane = threadIdx.x & 31, warp = threadIdx.x >> 5;

    float kw = klnw[h * 32 + lane], kb = klnb[h * 32 + lane];
    float vw = vlnw[h * 32 + lane], vb = vlnb[h * 32 + lane];

    float acc[32];
#pragma unroll
    for (int d = 0; d < 32; d++) acc[d] = 0.f;

    int n0 = blockIdx.x * 2048 + warp * 256;
    const float* base0 = g_qkv + ((size_t)b * NN + n0) * 576 + h * 96;

    for (int i = 0; i < 256; i++) {
        const float* base = base0 + (size_t)i * 576;
        float kx = base[32 + lane];
        float vx = base[64 + lane];

        float km = warp_sum(kx) * (1.0f / 32.0f);
        float ktv = kx - km;
        float ks = sqrtf(warp_sum(ktv * ktv) * (1.0f / 31.0f));   // ddof=1
        float lnk = kw * (ktv / (ks + 1e-5f)) + kb;

        float vm = warp_sum(vx) * (1.0f / 32.0f);
        float vtv = vx - vm;
        float vs = sqrtf(warp_sum(vtv * vtv) * (1.0f / 31.0f));
        float lnv = vw * (vtv / (vs + 1e-5f)) + vb;

#pragma unroll
        for (int d = 0; d < 32; d++)
            acc[d] = fmaf(__shfl_sync(0xffffffffu, lnk, d), lnv, acc[d]);
    }

    __shared__ float red[8][32][33];
#pragma unroll
    for (int d = 0; d < 32; d++) red[warp][d][lane] = acc[d];
    __syncthreads();

    for (int i = threadIdx.x; i < 1024; i += 256) {
        int d = i >> 5, e = i & 31;
        float s = 0.f;
#pragma unroll
        for (int w = 0; w < 8; w++) s += red[w][d][e];
        atomicAdd(&g_kv[(bh * 32 + d) * 32 + e], s * (1.0f / 65536.0f));
    }
}

// attn[r][32h+e] = sum_d q[r][h][d] * kv[b][h][d][e] + x[r][32h+e]  -> g_ret
// block handles 256 rows (single batch), warp-per-row
__global__ __launch_bounds__(256) void attn_kernel(const float* __restrict__ x)
{
    __shared__ float kvs[HH][32][33];
    int r0 = blockIdx.x * 256;
    int b = r0 / NN;

    for (int i = threadIdx.x; i < HH * 1024; i += 256) {
        int h = i >> 10, rem = i & 1023, d = rem >> 5, e = rem & 31;
        kvs[h][d][e] = g_kv[((b * HH + h) * 32 + d) * 32 + e];
    }
    __syncthreads();

    int lane = threadIdx.x & 31, warp = threadIdx.x >> 5;
    for (int i = 0; i < 32; i++) {
        size_t r = (size_t)r0 + warp * 32 + i;
        const float* qrow = g_qkv + r * 576;
        const float* xrow = x + r * 192;
        float* orow = g_ret + r * 192;
#pragma unroll
        for (int h = 0; h < HH; h++) {
            float q = qrow[96 * h + lane];
            float a = 0.f;
#pragma unroll
            for (int d = 0; d < 32; d++)
                a = fmaf(__shfl_sync(0xffffffffu, q, d), kvs[h][d][lane], a);
            orow[32 * h + lane] = a + xrow[32 * h + lane];
        }
    }
}

extern "C" void kernel_launch(void* const* d_in, const int* in_sizes, int n_in,
                              void* d_out, int out_size)
{
    const float* x     = (const float*)d_in[0];
    const float* qkv_w = (const float*)d_in[1];
    const float* qkv_b = (const float*)d_in[2];
    const float* o1_w  = (const float*)d_in[3];
    const float* o1_b  = (const float*)d_in[4];
    const float* o2_w  = (const float*)d_in[5];
    const float* o2_b  = (const float*)d_in[6];
    const float* klnw  = (const float*)d_in[7];
    const float* klnb  = (const float*)d_in[8];
    const float* vlnw  = (const float*)d_in[9];
    const float* vlnb  = (const float*)d_in[10];
    float* out = (float*)d_out;

    // 1) QKV projection -> g_qkv [R x 576]
    gemm192<0, 0, 1><<<dim3(RR / 64, 6), 256>>>(x, qkv_w, qkv_b, nullptr, nullptr, 576);
    // 2) zero kv accumulators
    zero_kv_kernel<<<24, 1024>>>();
    // 3) LN(k), LN(v) + kv reduction
    ln_kv_kernel<<<dim3(32, 24), 256>>>(klnw, klnb, vlnw, vlnb);
    // 4) attn = q @ kv + x -> g_ret
    attn_kernel<<<RR / 256, 256>>>(x);
    // 5) h = gelu(ret @ o1_w^T + o1_b) -> g_h
    gemm192<1, 1, 2><<<dim3(RR / 64, 2), 256>>>(nullptr, o1_w, o1_b, nullptr, nullptr, 192);
    // 6) out = h @ o2_w^T + o2_b + x
    gemm192<2, 2, 0><<<dim3(RR / 64, 2), 256>>>(nullptr, o2_w, o2_b, out, x, 192);
}

// round 2
// speedup vs baseline: 1.0572x; 1.0572x over previous
#include <cuda_runtime.h>
#include <math.h>

#define RR 262144   // B*N
#define NN 65536
#define CC 192
#define HH 6
#define DD 32

// Scratch (device globals: no allocation in kernel_launch)
__device__ float g_qkv[RR * 576];   // ~604 MB
__device__ float g_ret[RR * CC];    // ~201 MB
__device__ float g_h[RR * CC];      // ~201 MB
__device__ float g_kv[4 * HH * DD * DD];  // [b][h][d][e]

typedef unsigned long long u64;

__device__ __forceinline__ void fma2(u64 &d, u64 a, u64 b) {
    asm("fma.rn.f32x2 %0, %1, %2, %3;" : "=l"(d) : "l"(a), "l"(b), "l"(d));
}
__device__ __forceinline__ float2 unpack2(u64 v) {
    float2 r;
    asm("mov.b64 {%0, %1}, %2;" : "=f"(r.x), "=f"(r.y) : "l"(v));
    return r;
}

__device__ __forceinline__ float warp_sum(float v) {
    v += __shfl_xor_sync(0xffffffffu, v, 16);
    v += __shfl_xor_sync(0xffffffffu, v, 8);
    v += __shfl_xor_sync(0xffffffffu, v, 4);
    v += __shfl_xor_sync(0xffffffffu, v, 2);
    v += __shfl_xor_sync(0xffffffffu, v, 1);
    return v;
}

// K=192 GEMM with f32x2 packed FMA.
// CTA tile: 128 rows x 96 cols, 256 threads, thread = 8 rows x 6 cols.
// Accumulators packed over ROW pairs (A transposed in smem -> LDS.64 row pairs,
// W duplicated in smem -> LDS.64 dup pairs, zero pack instructions in loop).
// EPI: 0 = none, 1 = exact gelu, 2 = +resid
// ASEL: 0 = Aext, 1 = g_ret, 2 = g_h ; OSEL: 0 = Oext, 1 = g_qkv, 2 = g_h
template<int EPI, int ASEL, int OSEL>
__global__ __launch_bounds__(256) void gemm192(
    const float* __restrict__ Aext, const float* __restrict__ W,
    const float* __restrict__ bias, float* __restrict__ Oext,
    const float* __restrict__ resid, int ncols)
{
    const float* A = (ASEL == 0) ? Aext : (ASEL == 1 ? g_ret : g_h);
    float* OUT = (OSEL == 0) ? Oext : (OSEL == 1 ? g_qkv : g_h);

    __shared__ float As[32][132];   // [k][row], pad 132 (528B rows, 8B aligned)
    __shared__ float Ws[32][200];   // [k][2*col] value-duplicated, 800B rows

    int row0 = blockIdx.x * 128;
    int c0 = blockIdx.y * 96;
    int tid = threadIdx.x;
    int ty = tid >> 4, tx = tid & 15;   // ty: row group (8 rows), tx: col lane

    u64 acc[4][6];
#pragma unroll
    for (int i = 0; i < 4; i++)
#pragma unroll
        for (int j = 0; j < 6; j++) acc[i][j] = 0ULL;

    for (int kt = 0; kt < 192; kt += 32) {
        // A tile: 128 rows x 32 k = 1024 float4, transpose into As[k][row]
        for (int i = tid; i < 1024; i += 256) {
            int r = i >> 3, kq = i & 7;
            float4 v = *(const float4*)(A + (size_t)(row0 + r) * 192 + kt + kq * 4);
            As[kq * 4 + 0][r] = v.x;
            As[kq * 4 + 1][r] = v.y;
            As[kq * 4 + 2][r] = v.z;
            As[kq * 4 + 3][r] = v.w;
        }
        // W tile: 96 cols x 32 k = 768 float4, duplicated into Ws[k][2c],[2c+1]
        for (int i = tid; i < 768; i += 256) {
            int c = i >> 3, kq = i & 7;
            float4 v = *(const float4*)(W + (size_t)(c0 + c) * 192 + kt + kq * 4);
            Ws[kq * 4 + 0][2 * c] = v.x; Ws[kq * 4 + 0][2 * c + 1] = v.x;
            Ws[kq * 4 + 1][2 * c] = v.y; Ws[kq * 4 + 1][2 * c + 1] = v.y;
            Ws[kq * 4 + 2][2 * c] = v.z; Ws[kq * 4 + 2][2 * c + 1] = v.z;
            Ws[kq * 4 + 3][2 * c] = v.w; Ws[kq * 4 + 3][2 * c + 1] = v.w;
        }
        __syncthreads();

#pragma unroll 8
        for (int k = 0; k < 32; k++) {
            u64 a[4], b[6];
#pragma unroll
            for (int i2 = 0; i2 < 4; i2++)
                a[i2] = *(const u64*)&As[k][ty * 8 + 2 * i2];
#pragma unroll
            for (int j = 0; j < 6; j++)
                b[j] = *(const u64*)&Ws[k][2 * (tx + 16 * j)];
#pragma unroll
            for (int i2 = 0; i2 < 4; i2++)
#pragma unroll
                for (int j = 0; j < 6; j++)
                    fma2(acc[i2][j], a[i2], b[j]);
        }
        __syncthreads();
    }

#pragma unroll
    for (int j = 0; j < 6; j++) {
        int c = c0 + tx + 16 * j;
        float bi = bias[c];
#pragma unroll
        for (int i2 = 0; i2 < 4; i2++) {
            float2 p = unpack2(acc[i2][j]);
            size_t r = (size_t)row0 + ty * 8 + 2 * i2;
            float v0 = p.x + bi;
            float v1 = p.y + bi;
            if (EPI == 1) {
                v0 = 0.5f * v0 * (1.0f + erff(v0 * 0.70710678118654752440f));
                v1 = 0.5f * v1 * (1.0f + erff(v1 * 0.70710678118654752440f));
            }
            if (EPI == 2) {
                v0 += resid[r * ncols + c];
                v1 += resid[(r + 1) * ncols + c];
            }
            OUT[r * ncols + c] = v0;
            OUT[(r + 1) * ncols + c] = v1;
        }
    }
}

__global__ void zero_kv_kernel() {
    int i = blockIdx.x * blockDim.x + threadIdx.x;
    if (i < 4 * HH * DD * DD) g_kv[i] = 0.f;
}

// LayerNorm(k), LayerNorm(v) then kv[b,h,d,e] += ln_k[d]*ln_v[e], summed over n, /N.
__global__ __launch_bounds__(256) void ln_kv_kernel(
    const float* __restrict__ klnw, const float* __restrict__ klnb,
    const float* __restrict__ vlnw, const float* __restrict__ vlnb)
{
    int bh = blockIdx.y;
    int b = bh / HH, h = bh - b * HH;
    int lane = threadIdx.x & 31, warp = threadIdx.x >> 5;

    float kw = klnw[h * 32 + lane], kb = klnb[h * 32 + lane];
    float vw = vlnw[h * 32 + lane], vb = vlnb[h * 32 + lane];

    float acc[32];
#pragma unroll
    for (int d = 0; d < 32; d++) acc[d] = 0.f;

    int n0 = blockIdx.x * 2048 + warp * 256;
    const float* base0 = g_qkv + ((size_t)b * NN + n0) * 576 + h * 96;

    for (int i = 0; i < 256; i++) {
        const float* base = base0 + (size_t)i * 576;
        float kx = base[32 + lane];
        float vx = base[64 + lane];

        float km = warp_sum(kx) * (1.0f / 32.0f);
        float ktv = kx - km;
        float ks = sqrtf(warp_sum(ktv * ktv) * (1.0f / 31.0f));   // ddof=1
        float lnk = kw * (ktv / (ks + 1e-5f)) + kb;

        float vm = warp_sum(vx) * (1.0f / 32.0f);
        float vtv = vx - vm;
        float vs = sqrtf(warp_sum(vtv * vtv) * (1.0f / 31.0f));
        float lnv = vw * (vtv / (vs + 1e-5f)) + vb;

#pragma unroll
        for (int d = 0; d < 32; d++)
            acc[d] = fmaf(__shfl_sync(0xffffffffu, lnk, d), lnv, acc[d]);
    }

    __shared__ float red[8][32][33];
#pragma unroll
    for (int d = 0; d < 32; d++) red[warp][d][lane] = acc[d];
    __syncthreads();

    for (int i = threadIdx.x; i < 1024; i += 256) {
        int d = i >> 5, e = i & 31;
        float s = 0.f;
#pragma unroll
        for (int w = 0; w < 8; w++) s += red[w][d][e];
        atomicAdd(&g_kv[(bh * 32 + d) * 32 + e], s * (1.0f / 65536.0f));
    }
}

// attn[r][32h+e] = sum_d q[r][h][d] * kv[b][h][d][e] + x[r][32h+e]  -> g_ret
// GEMM-style: grid (RR/128, HH), block 256. Tile 128 rows x 32 cols, k = 32.
// Thread: 8 rows x 2 cols via f32x2 row-pair accumulators.
__global__ __launch_bounds__(256) void attn_kernel(const float* __restrict__ x)
{
    __shared__ float qs[32][132];   // [d][row]
    __shared__ float kvd[32][66];   // [d][2e] duplicated

    int h = blockIdx.y;
    int r0 = blockIdx.x * 128;
    int b = r0 / NN;
    int tid = threadIdx.x;
    int ty = tid >> 4, tx = tid & 15;

    for (int i = tid; i < 4096; i += 256) {
        int r = i >> 5, d = i & 31;
        qs[d][r] = g_qkv[(size_t)(r0 + r) * 576 + h * 96 + d];
    }
    for (int i = tid; i < 1024; i += 256) {
        int d = i >> 5, e = i & 31;
        float v = g_kv[((b * HH + h) * 32 + d) * 32 + e];
        kvd[d][2 * e] = v;
        kvd[d][2 * e + 1] = v;
    }
    __syncthreads();

    u64 acc[4][2];
#pragma unroll
    for (int i = 0; i < 4; i++) { acc[i][0] = 0ULL; acc[i][1] = 0ULL; }

#pragma unroll 8
    for (int d = 0; d < 32; d++) {
        u64 a[4];
#pragma unroll
        for (int i2 = 0; i2 < 4; i2++)
            a[i2] = *(const u64*)&qs[d][ty * 8 + 2 * i2];
        u64 b0 = *(const u64*)&kvd[d][2 * tx];
        u64 b1 = *(const u64*)&kvd[d][2 * (tx + 16)];
#pragma unroll
        for (int i2 = 0; i2 < 4; i2++) {
            fma2(acc[i2][0], a[i2], b0);
            fma2(acc[i2][1], a[i2], b1);
        }
    }

#pragma unroll
    for (int jc = 0; jc < 2; jc++) {
        int e = tx + 16 * jc;
#pragma unroll
        for (int i2 = 0; i2 < 4; i2++) {
            float2 p = unpack2(acc[i2][jc]);
            size_t r = (size_t)r0 + ty * 8 + 2 * i2;
            g_ret[r * 192 + h * 32 + e] = p.x + x[r * 192 + h * 32 + e];
            g_ret[(r + 1) * 192 + h * 32 + e] = p.y + x[(r + 1) * 192 + h * 32 + e];
        }
    }
}

extern "C" void kernel_launch(void* const* d_in, const int* in_sizes, int n_in,
                              void* d_out, int out_size)
{
    const float* x     = (const float*)d_in[0];
    const float* qkv_w = (const float*)d_in[1];
    const float* qkv_b = (const float*)d_in[2];
    const float* o1_w  = (const float*)d_in[3];
    const float* o1_b  = (const float*)d_in[4];
    const float* o2_w  = (const float*)d_in[5];
    const float* o2_b  = (const float*)d_in[6];
    const float* klnw  = (const float*)d_in[7];
    const float* klnb  = (const float*)d_in[8];
    const float* vlnw  = (const float*)d_in[9];
    const float* vlnb  = (const float*)d_in[10];
    float* out = (float*)d_out;

    // 1) QKV projection -> g_qkv [R x 576]
    gemm192<0, 0, 1><<<dim3(RR / 128, 6), 256>>>(x, qkv_w, qkv_b, nullptr, nullptr, 576);
    // 2) zero kv accumulators
    zero_kv_kernel<<<24, 1024>>>();
    // 3) LN(k), LN(v) + kv reduction
    ln_kv_kernel<<<dim3(32, 24), 256>>>(klnw, klnb, vlnw, vlnb);
    // 4) attn = q @ kv + x -> g_ret
    attn_kernel<<<dim3(RR / 128, HH), 256>>>(x);
    // 5) h = gelu(ret @ o1_w^T + o1_b) -> g_h
    gemm192<1, 1, 2><<<dim3(RR / 128, 2), 256>>>(nullptr, o1_w, o1_b, nullptr, nullptr, 192);
    // 6) out = h @ o2_w^T + o2_b + x
    gemm192<2, 2, 0><<<dim3(RR / 128, 2), 256>>>(nullptr, o2_w, o2_b, out, x, 192);
}

// round 4
// speedup vs baseline: 1.2805x; 1.2113x over previous
#include <cuda_runtime.h>
#include <cuda_bf16.h>
#include <math.h>
#include <stdint.h>

#define RR 262144   // B*N
#define NN 65536
#define CC 192
#define HH 6
#define DD 32

// Scratch (device globals: no allocation in kernel_launch)
__device__ float g_qkv[RR * 576];   // ~604 MB
__device__ float g_ret[RR * CC];    // ~201 MB
__device__ float g_h[RR * CC];      // ~201 MB
__device__ float g_kv[4 * HH * DD * DD];  // [b][h][d][e]

typedef unsigned long long u64;

__device__ __forceinline__ uint32_t smem_u32(const void* p) {
    uint32_t a;
    asm("{ .reg .u64 t; cvta.to.shared.u64 t, %1; cvt.u32.u64 %0, t; }" : "=r"(a) : "l"(p));
    return a;
}

__device__ __forceinline__ void ldsm_x4(uint32_t a[4], uint32_t addr) {
    asm volatile("ldmatrix.sync.aligned.m8n8.x4.shared.b16 {%0,%1,%2,%3}, [%4];"
        : "=r"(a[0]), "=r"(a[1]), "=r"(a[2]), "=r"(a[3]) : "r"(addr));
}
__device__ __forceinline__ void ldsm_x2(uint32_t a[2], uint32_t addr) {
    asm volatile("ldmatrix.sync.aligned.m8n8.x2.shared.b16 {%0,%1}, [%2];"
        : "=r"(a[0]), "=r"(a[1]) : "r"(addr));
}
__device__ __forceinline__ void mma_bf16(float c[4], const uint32_t a[4], const uint32_t b[2]) {
    asm volatile(
        "mma.sync.aligned.m16n8k16.row.col.f32.bf16.bf16.f32 "
        "{%0,%1,%2,%3}, {%4,%5,%6,%7}, {%8,%9}, {%0,%1,%2,%3};"
        : "+f"(c[0]), "+f"(c[1]), "+f"(c[2]), "+f"(c[3])
        : "r"(a[0]), "r"(a[1]), "r"(a[2]), "r"(a[3]), "r"(b[0]), "r"(b[1]));
}

// ====================== HMMA GEMM (bf16 2-term split, 3 passes) ======================
// D[128, 96] = A[128,192] * W[96,192]^T, fp32 acc.
// smem: row pitch 200 bf16 = 400B (192 data + 8 pad -> ldmatrix conflict-free).
#define PITCH 200
#define OFF_A_HI 0
#define OFF_A_LO 51200
#define OFF_W_HI 102400
#define OFF_W_LO 140800
#define SMEM_DYN 179200

union BF4 { __nv_bfloat16 h[4]; u64 u; };

__device__ __forceinline__ void split4(float4 v, BF4& hi, BF4& lo) {
    float f[4] = {v.x, v.y, v.z, v.w};
#pragma unroll
    for (int j = 0; j < 4; j++) {
        __nv_bfloat16 h = __float2bfloat16(f[j]);
        hi.h[j] = h;
        lo.h[j] = __float2bfloat16(f[j] - __bfloat162float(h));
    }
}

// EPI: 0 = none, 1 = exact gelu, 2 = +resid
// ASEL: 0 = Aext, 1 = g_ret, 2 = g_h ; OSEL: 0 = Oext, 1 = g_qkv, 2 = g_h
// grid: (ncols/96, RR/128)  [col tile fastest -> L2 reuse of A]
template<int EPI, int ASEL, int OSEL>
__global__ __launch_bounds__(256) void gemm_tc(
    const float* __restrict__ Aext, const float* __restrict__ W,
    const float* __restrict__ bias, float* __restrict__ Oext,
    const float* __restrict__ resid, int ncols)
{
    const float* A = (ASEL == 0) ? Aext : (ASEL == 1 ? g_ret : g_h);
    float* OUT = (OSEL == 0) ? Oext : (OSEL == 1 ? g_qkv : g_h);

    extern __shared__ char sm[];
    uint32_t sbase = smem_u32(sm);

    int tid = threadIdx.x;
    int c0 = blockIdx.x * 96;
    int row0 = blockIdx.y * 128;

    // ---- load + split A tile: 128 rows x 192 k ----
    for (int i = tid; i < 128 * 48; i += 256) {
        int r = i / 48, k4 = i - (i / 48) * 48;
        float4 v = *(const float4*)(A + (size_t)(row0 + r) * 192 + k4 * 4);
        BF4 hi, lo; split4(v, hi, lo);
        int off = r * 400 + k4 * 8;
        *(u64*)(sm + OFF_A_HI + off) = hi.u;
        *(u64*)(sm + OFF_A_LO + off) = lo.u;
    }
    // ---- load + split W tile: 96 cols x 192 k ----
    for (int i = tid; i < 96 * 48; i += 256) {
        int c = i / 48, k4 = i - (i / 48) * 48;
        float4 v = *(const float4*)(W + (size_t)(c0 + c) * 192 + k4 * 4);
        BF4 hi, lo; split4(v, hi, lo);
        int off = c * 400 + k4 * 8;
        *(u64*)(sm + OFF_W_HI + off) = hi.u;
        *(u64*)(sm + OFF_W_LO + off) = lo.u;
    }
    __syncthreads();

    int l = tid & 31, wid = tid >> 5;
    int warp_m = wid >> 2;        // 0..1 : 64 rows each
    int warp_n = wid & 3;         // 0..3 : 24 cols each

    float acc[4][3][4];
#pragma unroll
    for (int mt = 0; mt < 4; mt++)
#pragma unroll
        for (int nt = 0; nt < 3; nt++)
#pragma unroll
            for (int j = 0; j < 4; j++) acc[mt][nt][j] = 0.f;

    // ldmatrix lane addressing
    int rowA = warp_m * 64 + (l & 7) + ((l >> 3) & 1) * 8;
    int kofsA = (l >> 4) * 8;
    int rowB = warp_n * 24 + (l & 7);
    int kofsB = ((l >> 3) & 1) * 8;

#pragma unroll
    for (int ks = 0; ks < 12; ks++) {
        int k0 = ks * 16;
        uint32_t ahi[4][4], alo[4][4], bhi[3][2], blo[3][2];
        uint32_t aoff = (uint32_t)(rowA * 400 + (k0 + kofsA) * 2);
#pragma unroll
        for (int mt = 0; mt < 4; mt++) {
            ldsm_x4(ahi[mt], sbase + OFF_A_HI + aoff + mt * (16 * 400));
            ldsm_x4(alo[mt], sbase + OFF_A_LO + aoff + mt * (16 * 400));
        }
        uint32_t boff = (uint32_t)(rowB * 400 + (k0 + kofsB) * 2);
#pragma unroll
        for (int nt = 0; nt < 3; nt++) {
            ldsm_x2(bhi[nt], sbase + OFF_W_HI + boff + nt * (8 * 400));
            ldsm_x2(blo[nt], sbase + OFF_W_LO + boff + nt * (8 * 400));
        }
#pragma unroll
        for (int mt = 0; mt < 4; mt++)
#pragma unroll
            for (int nt = 0; nt < 3; nt++)
                mma_bf16(acc[mt][nt], ahi[mt], bhi[nt]);
#pragma unroll
        for (int mt = 0; mt < 4; mt++)
#pragma unroll
            for (int nt = 0; nt < 3; nt++)
                mma_bf16(acc[mt][nt], alo[mt], bhi[nt]);
#pragma unroll
        for (int mt = 0; mt < 4; mt++)
#pragma unroll
            for (int nt = 0; nt < 3; nt++)
                mma_bf16(acc[mt][nt], ahi[mt], blo[nt]);
    }

    // ---- epilogue: c0,c1 -> (row, col..col+1); c2,c3 -> (row+8, ...) ----
#pragma unroll
    for (int mt = 0; mt < 4; mt++) {
#pragma unroll
        for (int nt = 0; nt < 3; nt++) {
            int col = c0 + warp_n * 24 + nt * 8 + 2 * (l & 3);
            float b0 = bias[col], b1 = bias[col + 1];
            size_t r0g = (size_t)row0 + warp_m * 64 + mt * 16 + (l >> 2);
#pragma unroll
            for (int half = 0; half < 2; half++) {
                size_t r = r0g + half * 8;
                float v0 = acc[mt][nt][half * 2 + 0] + b0;
                float v1 = acc[mt][nt][half * 2 + 1] + b1;
                if (EPI == 1) {
                    v0 = 0.5f * v0 * (1.0f + erff(v0 * 0.70710678118654752440f));
                    v1 = 0.5f * v1 * (1.0f + erff(v1 * 0.70710678118654752440f));
                }
                if (EPI == 2) {
                    v0 += resid[r * ncols + col];
                    v1 += resid[r * ncols + col + 1];
                }
                OUT[r * ncols + col] = v0;
                OUT[r * ncols + col + 1] = v1;
            }
        }
    }
}

// ============================ non-GEMM kernels ============================
__device__ __forceinline__ void fma2(u64 &d, u64 a, u64 b) {
    asm("fma.rn.f32x2 %0, %1, %2, %3;" : "=l"(d) : "l"(a), "l"(b), "l"(d));
}
__device__ __forceinline__ float2 unpack2(u64 v) {
    float2 r;
    asm("mov.b64 {%0, %1}, %2;" : "=f"(r.x), "=f"(r.y) : "l"(v));
    return r;
}
__device__ __forceinline__ float warp_sum(float v) {
    v += __shfl_xor_sync(0xffffffffu, v, 16);
    v += __shfl_xor_sync(0xffffffffu, v, 8);
    v += __shfl_xor_sync(0xffffffffu, v, 4);
    v += __shfl_xor_sync(0xffffffffu, v, 2);
    v += __shfl_xor_sync(0xffffffffu, v, 1);
    return v;
}

__global__ void zero_kv_kernel() {
    int i = blockIdx.x * blockDim.x + threadIdx.x;
    if (i < 4 * HH * DD * DD) g_kv[i] = 0.f;
}

__global__ __launch_bounds__(256) void ln_kv_kernel(
    const float* __restrict__ klnw, const float* __restrict__ klnb,
    const float* __restrict__ vlnw, const float* __restrict__ vlnb)
{
    int bh = blockIdx.y;
    int b = bh / HH, h = bh - b * HH;
    int lane = threadIdx.x & 31, warp = threadIdx.x >> 5;

    float kw = klnw[h * 32 + lane], kb = klnb[h * 32 + lane];
    float vw = vlnw[h * 32 + lane], vb = vlnb[h * 32 + lane];

    float acc[32];
#pragma unroll
    for (int d = 0; d < 32; d++) acc[d] = 0.f;

    int n0 = blockIdx.x * 2048 + warp * 256;
    const float* base0 = g_qkv + ((size_t)b * NN + n0) * 576 + h * 96;

    for (int i = 0; i < 256; i++) {
        const float* base = base0 + (size_t)i * 576;
        float kx = base[32 + lane];
        float vx = base[64 + lane];

        float km = warp_sum(kx) * (1.0f / 32.0f);
        float ktv = kx - km;
        float ks = sqrtf(warp_sum(ktv * ktv) * (1.0f / 31.0f));   // ddof=1
        float lnk = kw * (ktv / (ks + 1e-5f)) + kb;

        float vm = warp_sum(vx) * (1.0f / 32.0f);
        float vtv = vx - vm;
        float vs = sqrtf(warp_sum(vtv * vtv) * (1.0f / 31.0f));
        float lnv = vw * (vtv / (vs + 1e-5f)) + vb;

#pragma unroll
        for (int d = 0; d < 32; d++)
            acc[d] = fmaf(__shfl_sync(0xffffffffu, lnk, d), lnv, acc[d]);
    }

    __shared__ float red[8][32][33];
#pragma unroll
    for (int d = 0; d < 32; d++) red[warp][d][lane] = acc[d];
    __syncthreads();

    for (int i = threadIdx.x; i < 1024; i += 256) {
        int d = i >> 5, e = i & 31;
        float s = 0.f;
#pragma unroll
        for (int w = 0; w < 8; w++) s += red[w][d][e];
        atomicAdd(&g_kv[(bh * 32 + d) * 32 + e], s * (1.0f / 65536.0f));
    }
}

__global__ __launch_bounds__(256) void attn_kernel(const float* __restrict__ x)
{
    __shared__ float qs[32][132];   // [d][row]
    __shared__ float kvd[32][66];   // [d][2e] duplicated

    int h = blockIdx.y;
    int r0 = blockIdx.x * 128;
    int b = r0 / NN;
    int tid = threadIdx.x;
    int ty = tid >> 4, tx = tid & 15;

    for (int i = tid; i < 4096; i += 256) {
        int r = i >> 5, d = i & 31;
        qs[d][r] = g_qkv[(size_t)(r0 + r) * 576 + h * 96 + d];
    }
    for (int i = tid; i < 1024; i += 256) {
        int d = i >> 5, e = i & 31;
        float v = g_kv[((b * HH + h) * 32 + d) * 32 + e];
        kvd[d][2 * e] = v;
        kvd[d][2 * e + 1] = v;
    }
    __syncthreads();

    u64 acc[4][2];
#pragma unroll
    for (int i = 0; i < 4; i++) { acc[i][0] = 0ULL; acc[i][1] = 0ULL; }

#pragma unroll 8
    for (int d = 0; d < 32; d++) {
        u64 a[4];
#pragma unroll
        for (int i2 = 0; i2 < 4; i2++)
            a[i2] = *(const u64*)&qs[d][ty * 8 + 2 * i2];
        u64 b0 = *(const u64*)&kvd[d][2 * tx];
        u64 b1 = *(const u64*)&kvd[d][2 * (tx + 16)];
#pragma unroll
        for (int i2 = 0; i2 < 4; i2++) {
            fma2(acc[i2][0], a[i2], b0);
            fma2(acc[i2][1], a[i2], b1);
        }
    }

#pragma unroll
    for (int jc = 0; jc < 2; jc++) {
        int e = tx + 16 * jc;
#pragma unroll
        for (int i2 = 0; i2 < 4; i2++) {
            float2 p = unpack2(acc[i2][jc]);
            size_t r = (size_t)r0 + ty * 8 + 2 * i2;
            g_ret[r * 192 + h * 32 + e] = p.x + x[r * 192 + h * 32 + e];
            g_ret[(r + 1) * 192 + h * 32 + e] = p.y + x[(r + 1) * 192 + h * 32 + e];
        }
    }
}

extern "C" void kernel_launch(void* const* d_in, const int* in_sizes, int n_in,
                              void* d_out, int out_size)
{
    const float* x     = (const float*)d_in[0];
    const float* qkv_w = (const float*)d_in[1];
    const float* qkv_b = (const float*)d_in[2];
    const float* o1_w  = (const float*)d_in[3];
    const float* o1_b  = (const float*)d_in[4];
    const float* o2_w  = (const float*)d_in[5];
    const float* o2_b  = (const float*)d_in[6];
    const float* klnw  = (const float*)d_in[7];
    const float* klnb  = (const float*)d_in[8];
    const float* vlnw  = (const float*)d_in[9];
    const float* vlnb  = (const float*)d_in[10];
    float* out = (float*)d_out;

    cudaFuncSetAttribute(gemm_tc<0, 0, 1>, cudaFuncAttributeMaxDynamicSharedMemorySize, SMEM_DYN);
    cudaFuncSetAttribute(gemm_tc<1, 1, 2>, cudaFuncAttributeMaxDynamicSharedMemorySize, SMEM_DYN);
    cudaFuncSetAttribute(gemm_tc<2, 2, 0>, cudaFuncAttributeMaxDynamicSharedMemorySize, SMEM_DYN);

    // 1) QKV projection -> g_qkv [R x 576]   (col tile fastest for L2 reuse of A)
    gemm_tc<0, 0, 1><<<dim3(6, RR / 128), 256, SMEM_DYN>>>(x, qkv_w, qkv_b, nullptr, nullptr, 576);
    // 2) zero kv accumulators
    zero_kv_kernel<<<24, 1024>>>();
    // 3) LN(k), LN(v) + kv reduction
    ln_kv_kernel<<<dim3(32, 24), 256>>>(klnw, klnb, vlnw, vlnb);
    // 4) attn = q @ kv + x -> g_ret
    attn_kernel<<<dim3(RR / 128, HH), 256>>>(x);
    // 5) h = gelu(ret @ o1_w^T + o1_b) -> g_h
    gemm_tc<1, 1, 2><<<dim3(2, RR / 128), 256, SMEM_DYN>>>(nullptr, o1_w, o1_b, nullptr, nullptr, 192);
    // 6) out = h @ o2_w^T + o2_b + x
    gemm_tc<2, 2, 0><<<dim3(2, RR / 128), 256, SMEM_DYN>>>(nullptr, o2_w, o2_b, out, x, 192);
}

// round 5
// speedup vs baseline: 1.9925x; 1.5560x over previous
#include <cuda_runtime.h>
#include <cuda_bf16.h>
#include <math.h>
#include <stdint.h>

#define RR 262144   // B*N
#define NN 65536
#define HH 6
#define DD 32

typedef unsigned long long u64;

// ============================ scratch (device globals) ============================
__device__ float g_qkv[RR * 576];                       // fp32 qkv
__device__ float g_kv[4 * HH * DD * DD];
__device__ __nv_bfloat16 g_xh[RR * 192], g_xl[RR * 192];   // x split
__device__ __nv_bfloat16 g_rh[RR * 192], g_rl[RR * 192];   // ret split (attn out)
__device__ __nv_bfloat16 g_hh[RR * 192], g_hl[RR * 192];   // h split (o1 out)
__device__ __nv_bfloat16 g_wh[960 * 192], g_wl[960 * 192]; // weights: qkv(0..575), o1(576..767), o2(768..959)

// ============================ helpers ============================
__device__ __forceinline__ uint32_t smem_u32(const void* p) {
    uint32_t a;
    asm("{ .reg .u64 t; cvta.to.shared.u64 t, %1; cvt.u32.u64 %0, t; }" : "=r"(a) : "l"(p));
    return a;
}
__device__ __forceinline__ void ldsm_x4(uint32_t a[4], uint32_t addr) {
    asm volatile("ldmatrix.sync.aligned.m8n8.x4.shared.b16 {%0,%1,%2,%3}, [%4];"
        : "=r"(a[0]), "=r"(a[1]), "=r"(a[2]), "=r"(a[3]) : "r"(addr));
}
__device__ __forceinline__ void ldsm_x2(uint32_t a[2], uint32_t addr) {
    asm volatile("ldmatrix.sync.aligned.m8n8.x2.shared.b16 {%0,%1}, [%2];"
        : "=r"(a[0]), "=r"(a[1]) : "r"(addr));
}
__device__ __forceinline__ void mma_bf16(float c[4], const uint32_t a[4], const uint32_t b[2]) {
    asm volatile(
        "mma.sync.aligned.m16n8k16.row.col.f32.bf16.bf16.f32 "
        "{%0,%1,%2,%3}, {%4,%5,%6,%7}, {%8,%9}, {%0,%1,%2,%3};"
        : "+f"(c[0]), "+f"(c[1]), "+f"(c[2]), "+f"(c[3])
        : "r"(a[0]), "r"(a[1]), "r"(a[2]), "r"(a[3]), "r"(b[0]), "r"(b[1]));
}
__device__ __forceinline__ void cpa16(uint32_t dst, const void* src) {
    asm volatile("cp.async.ca.shared.global [%0], [%1], 16;" :: "r"(dst), "l"(src));
}
__device__ __forceinline__ void cp_commit() {
    asm volatile("cp.async.commit_group;" ::: "memory");
}
template<int N> __device__ __forceinline__ void cp_wait() {
    asm volatile("cp.async.wait_group %0;" :: "n"(N) : "memory");
}

union BF4 { __nv_bfloat16 h[4]; u64 u; };
__device__ __forceinline__ void split4(float4 v, BF4& hi, BF4& lo) {
    float f[4] = {v.x, v.y, v.z, v.w};
#pragma unroll
    for (int j = 0; j < 4; j++) {
        __nv_bfloat16 h = __float2bfloat16(f[j]);
        hi.h[j] = h;
        lo.h[j] = __float2bfloat16(f[j] - __bfloat162float(h));
    }
}
__device__ __forceinline__ void split1(float v, __nv_bfloat16& h, __nv_bfloat16& l) {
    h = __float2bfloat16(v);
    l = __float2bfloat16(v - __bfloat162float(h));
}

// ============================ split kernels ============================
__global__ __launch_bounds__(256) void split_x_kernel(const float* __restrict__ src) {
    int stride = gridDim.x * blockDim.x;
    for (int i = blockIdx.x * blockDim.x + threadIdx.x; i < RR * 48; i += stride) {
        float4 v = ((const float4*)src)[i];
        BF4 hi, lo; split4(v, hi, lo);
        ((u64*)g_xh)[i] = hi.u;
        ((u64*)g_xl)[i] = lo.u;
    }
}
__global__ __launch_bounds__(256) void split_w_kernel(
    const float* __restrict__ qkvw, const float* __restrict__ o1w, const float* __restrict__ o2w)
{
    int stride = gridDim.x * blockDim.x;
    for (int i = blockIdx.x * blockDim.x + threadIdx.x; i < 960 * 48; i += stride) {
        float4 v;
        if (i < 27648)      v = ((const float4*)qkvw)[i];
        else if (i < 36864) v = ((const float4*)o1w)[i - 27648];
        else                v = ((const float4*)o2w)[i - 36864];
        BF4 hi, lo; split4(v, hi, lo);
        ((u64*)g_wh)[i] = hi.u;
        ((u64*)g_wl)[i] = lo.u;
    }
}

// ============================ HMMA GEMM ============================
// D[128 rows, NCT*96 cols] = A[128,192] * W^T (3-pass bf16 split, fp32 acc).
// A (pre-split bf16) resident full-K in smem; W streamed in 96-col x 96-k chunks,
// double-buffered via cp.async.
// smem: A_hi [128][200]b16 @0 (51200), A_lo @51200, W bufs @102400 (2 x 39936).
#define OFF_AL 51200
#define OFF_W  102400
#define WBUF   39936
#define WHALF  19968
#define SMEM_DYN 182272

__device__ __forceinline__ void load_w_chunk(uint32_t sbase, int wrow0, int n, int tid) {
    int ct = n >> 1, kc = n & 1, buf = n & 1;
    uint32_t wb = sbase + OFF_W + buf * WBUF;
    const char* bh = (const char*)g_wh;
    const char* bl = (const char*)g_wl;
    for (int i = tid; i < 96 * 12; i += 256) {
        int r = i / 12, j = i - (i / 12) * 12;
        size_t src = (size_t)(wrow0 + ct * 96 + r) * 384 + (size_t)kc * 192 + (size_t)j * 16;
        uint32_t dst = wb + r * 208 + j * 16;
        cpa16(dst, bh + src);
        cpa16(dst + WHALF, bl + src);
    }
}

// EPI: 0 = none (fp32 -> g_qkv), 1 = gelu (bf16 split -> g_hh/g_hl), 2 = +resid (fp32 -> Ofp_ext)
// ASEL: 0 = x split, 1 = ret split, 2 = h split
template<int EPI, int NCT, int ASEL>
__global__ __launch_bounds__(256) void gemm_hmma(
    int wrow0, const float* __restrict__ bias,
    float* __restrict__ Ofp_ext, const float* __restrict__ resid, int ncols)
{
    const __nv_bfloat16* Ah = (ASEL == 0) ? g_xh : (ASEL == 1 ? g_rh : g_hh);
    const __nv_bfloat16* Al = (ASEL == 0) ? g_xl : (ASEL == 1 ? g_rl : g_hl);
    float* Ofp = (EPI == 2) ? Ofp_ext : g_qkv;

    extern __shared__ char sm[];
    uint32_t sbase = smem_u32(sm);
    int tid = threadIdx.x;
    size_t row0 = (size_t)blockIdx.x * 128;

    // A tiles (hi & lo): 128 rows x 24 16B-chunks each
    {
        const char* ah = (const char*)Ah;
        const char* al = (const char*)Al;
        for (int i = tid; i < 128 * 24; i += 256) {
            int r = i / 24, j = i - (i / 24) * 24;
            size_t src = (row0 + r) * 384 + (size_t)j * 16;
            uint32_t dst = (uint32_t)(r * 400 + j * 16);
            cpa16(sbase + dst, ah + src);
            cpa16(sbase + OFF_AL + dst, al + src);
        }
    }
    load_w_chunk(sbase, wrow0, 0, tid);
    cp_commit();

    int l = tid & 31, wid = tid >> 5;
    int warp_m = wid >> 2;        // 0..1 : 64 rows
    int warp_n = wid & 3;         // 0..3 : 24 cols
    int rowA = warp_m * 64 + (l & 7) + ((l >> 3) & 1) * 8;
    int kofsA = (l >> 4) * 8;
    int rowB = warp_n * 24 + (l & 7);
    int kofsB = ((l >> 3) & 1) * 8;

    const int NCH = NCT * 2;
#pragma unroll 1
    for (int ct = 0; ct < NCT; ct++) {
        float acc[4][3][4];
#pragma unroll
        for (int mt = 0; mt < 4; mt++)
#pragma unroll
            for (int nt = 0; nt < 3; nt++)
#pragma unroll
                for (int j = 0; j < 4; j++) acc[mt][nt][j] = 0.f;

#pragma unroll
        for (int kc = 0; kc < 2; kc++) {
            int n = ct * 2 + kc;
            if (n + 1 < NCH) { load_w_chunk(sbase, wrow0, n + 1, tid); cp_commit(); cp_wait<1>(); }
            else cp_wait<0>();
            __syncthreads();

            uint32_t wb = sbase + OFF_W + (n & 1) * WBUF;
#pragma unroll
            for (int ksl = 0; ksl < 6; ksl++) {
                int ks = kc * 6 + ksl;
                uint32_t ahi[4][4], alo[4][4], bhi[3][2], blo[3][2];
                uint32_t aoff = sbase + (uint32_t)(rowA * 400 + (ks * 16 + kofsA) * 2);
#pragma unroll
                for (int mt = 0; mt < 4; mt++) {
                    ldsm_x4(ahi[mt], aoff + mt * (16 * 400));
                    ldsm_x4(alo[mt], OFF_AL + aoff + mt * (16 * 400));
                }
                uint32_t boff = wb + (uint32_t)(rowB * 208 + (ksl * 16 + kofsB) * 2);
#pragma unroll
                for (int nt = 0; nt < 3; nt++) {
                    ldsm_x2(bhi[nt], boff + nt * (8 * 208));
                    ldsm_x2(blo[nt], boff + WHALF + nt * (8 * 208));
                }
#pragma unroll
                for (int mt = 0; mt < 4; mt++)
#pragma unroll
                    for (int nt = 0; nt < 3; nt++)
                        mma_bf16(acc[mt][nt], ahi[mt], bhi[nt]);
#pragma unroll
                for (int mt = 0; mt < 4; mt++)
#pragma unroll
                    for (int nt = 0; nt < 3; nt++)
                        mma_bf16(acc[mt][nt], alo[mt], bhi[nt]);
#pragma unroll
                for (int mt = 0; mt < 4; mt++)
#pragma unroll
                    for (int nt = 0; nt < 3; nt++)
                        mma_bf16(acc[mt][nt], ahi[mt], blo[nt]);
            }
            __syncthreads();   // protect W buffer before next prefetch overwrites it
        }

        // ---- epilogue for this col tile ----
#pragma unroll
        for (int mt = 0; mt < 4; mt++) {
#pragma unroll
            for (int nt = 0; nt < 3; nt++) {
                int col = ct * 96 + warp_n * 24 + nt * 8 + 2 * (l & 3);
                float b0 = bias[col], b1 = bias[col + 1];
                size_t rg = row0 + warp_m * 64 + mt * 16 + (l >> 2);
#pragma unroll
                for (int half = 0; half < 2; half++) {
                    size_t r = rg + half * 8;
                    float v0 = acc[mt][nt][half * 2 + 0] + b0;
                    float v1 = acc[mt][nt][half * 2 + 1] + b1;
                    if (EPI == 1) {
                        v0 = 0.5f * v0 * (1.0f + erff(v0 * 0.70710678118654752440f));
                        v1 = 0.5f * v1 * (1.0f + erff(v1 * 0.70710678118654752440f));
                        __nv_bfloat162 ph, pl;
                        split1(v0, ph.x, pl.x);
                        split1(v1, ph.y, pl.y);
                        *(__nv_bfloat162*)&g_hh[r * 192 + col] = ph;
                        *(__nv_bfloat162*)&g_hl[r * 192 + col] = pl;
                    } else {
                        if (EPI == 2) {
                            v0 += resid[r * (size_t)ncols + col];
                            v1 += resid[r * (size_t)ncols + col + 1];
                        }
                        float2 p; p.x = v0; p.y = v1;
                        *(float2*)&Ofp[r * (size_t)ncols + col] = p;
                    }
                }
            }
        }
    }
}

// ============================ non-GEMM kernels ============================
__device__ __forceinline__ void fma2(u64 &d, u64 a, u64 b) {
    asm("fma.rn.f32x2 %0, %1, %2, %3;" : "=l"(d) : "l"(a), "l"(b), "l"(d));
}
__device__ __forceinline__ float2 unpack2(u64 v) {
    float2 r;
    asm("mov.b64 {%0, %1}, %2;" : "=f"(r.x), "=f"(r.y) : "l"(v));
    return r;
}
__device__ __forceinline__ float warp_sum(float v) {
    v += __shfl_xor_sync(0xffffffffu, v, 16);
    v += __shfl_xor_sync(0xffffffffu, v, 8);
    v += __shfl_xor_sync(0xffffffffu, v, 4);
    v += __shfl_xor_sync(0xffffffffu, v, 2);
    v += __shfl_xor_sync(0xffffffffu, v, 1);
    return v;
}

__global__ void zero_kv_kernel() {
    int i = blockIdx.x * blockDim.x + threadIdx.x;
    if (i < 4 * HH * DD * DD) g_kv[i] = 0.f;
}

__global__ __launch_bounds__(256) void ln_kv_kernel(
    const float* __restrict__ klnw, const float* __restrict__ klnb,
    const float* __restrict__ vlnw, const float* __restrict__ vlnb)
{
    int bh = blockIdx.y;
    int b = bh / HH, h = bh - b * HH;
    int lane = threadIdx.x & 31, warp = threadIdx.x >> 5;

    float kw = klnw[h * 32 + lane], kb = klnb[h * 32 + lane];
    float vw = vlnw[h * 32 + lane], vb = vlnb[h * 32 + lane];

    float acc[32];
#pragma unroll
    for (int d = 0; d < 32; d++) acc[d] = 0.f;

    int n0 = blockIdx.x * 2048 + warp * 256;
    const float* base0 = g_qkv + ((size_t)b * NN + n0) * 576 + h * 96;

    for (int i = 0; i < 256; i++) {
        const float* base = base0 + (size_t)i * 576;
        float kx = base[32 + lane];
        float vx = base[64 + lane];

        float km = warp_sum(kx) * (1.0f / 32.0f);
        float ktv = kx - km;
        float ks = sqrtf(warp_sum(ktv * ktv) * (1.0f / 31.0f));   // ddof=1
        float lnk = kw * (ktv / (ks + 1e-5f)) + kb;

        float vm = warp_sum(vx) * (1.0f / 32.0f);
        float vtv = vx - vm;
        float vs = sqrtf(warp_sum(vtv * vtv) * (1.0f / 31.0f));
        float lnv = vw * (vtv / (vs + 1e-5f)) + vb;

#pragma unroll
        for (int d = 0; d < 32; d++)
            acc[d] = fmaf(__shfl_sync(0xffffffffu, lnk, d), lnv, acc[d]);
    }

    __shared__ float red[8][32][33];
#pragma unroll
    for (int d = 0; d < 32; d++) red[warp][d][lane] = acc[d];
    __syncthreads();

    for (int i = threadIdx.x; i < 1024; i += 256) {
        int d = i >> 5, e = i & 31;
        float s = 0.f;
#pragma unroll
        for (int w = 0; w < 8; w++) s += red[w][d][e];
        atomicAdd(&g_kv[(bh * 32 + d) * 32 + e], s * (1.0f / 65536.0f));
    }
}

// attn: ret = q @ kv + x, written directly as bf16 hi/lo split for the o1 GEMM.
__global__ __launch_bounds__(256) void attn_kernel(const float* __restrict__ x)
{
    __shared__ float qs[32][132];   // [d][row]
    __shared__ float kvd[32][66];   // [d][2e] duplicated

    int h = blockIdx.y;
    int r0 = blockIdx.x * 128;
    int b = r0 / NN;
    int tid = threadIdx.x;
    int ty = tid >> 4, tx = tid & 15;

    for (int i = tid; i < 4096; i += 256) {
        int r = i >> 5, d = i & 31;
        qs[d][r] = g_qkv[(size_t)(r0 + r) * 576 + h * 96 + d];
    }
    for (int i = tid; i < 1024; i += 256) {
        int d = i >> 5, e = i & 31;
        float v = g_kv[((b * HH + h) * 32 + d) * 32 + e];
        kvd[d][2 * e] = v;
        kvd[d][2 * e + 1] = v;
    }
    __syncthreads();

    u64 acc[4][2];
#pragma unroll
    for (int i = 0; i < 4; i++) { acc[i][0] = 0ULL; acc[i][1] = 0ULL; }

#pragma unroll 8
    for (int d = 0; d < 32; d++) {
        u64 a[4];
#pragma unroll
        for (int i2 = 0; i2 < 4; i2++)
            a[i2] = *(const u64*)&qs[d][ty * 8 + 2 * i2];
        u64 b0 = *(const u64*)&kvd[d][2 * tx];
        u64 b1 = *(const u64*)&kvd[d][2 * (tx + 16)];
#pragma unroll
        for (int i2 = 0; i2 < 4; i2++) {
            fma2(acc[i2][0], a[i2], b0);
            fma2(acc[i2][1], a[i2], b1);
        }
    }

#pragma unroll
    for (int jc = 0; jc < 2; jc++) {
        int e = tx + 16 * jc;
#pragma unroll
        for (int i2 = 0; i2 < 4; i2++) {
            float2 p = unpack2(acc[i2][jc]);
            size_t r = (size_t)r0 + ty * 8 + 2 * i2;
            size_t i0 = r * 192 + h * 32 + e;
            size_t i1 = (r + 1) * 192 + h * 32 + e;
            float s0 = p.x + x[i0];
            float s1 = p.y + x[i1];
            __nv_bfloat16 h0, l0, h1, l1;
            split1(s0, h0, l0);
            split1(s1, h1, l1);
            g_rh[i0] = h0; g_rl[i0] = l0;
            g_rh[i1] = h1; g_rl[i1] = l1;
        }
    }
}

extern "C" void kernel_launch(void* const* d_in, const int* in_sizes, int n_in,
                              void* d_out, int out_size)
{
    const float* x     = (const float*)d_in[0];
    const float* qkv_w = (const float*)d_in[1];
    const float* qkv_b = (const float*)d_in[2];
    const float* o1_w  = (const float*)d_in[3];
    const float* o1_b  = (const float*)d_in[4];
    const float* o2_w  = (const float*)d_in[5];
    const float* o2_b  = (const float*)d_in[6];
    const float* klnw  = (const float*)d_in[7];
    const float* klnb  = (const float*)d_in[8];
    const float* vlnw  = (const float*)d_in[9];
    const float* vlnb  = (const float*)d_in[10];
    float* out = (float*)d_out;

    cudaFuncSetAttribute(gemm_hmma<0, 6, 0>, cudaFuncAttributeMaxDynamicSharedMemorySize, SMEM_DYN);
    cudaFuncSetAttribute(gemm_hmma<1, 2, 1>, cudaFuncAttributeMaxDynamicSharedMemorySize, SMEM_DYN);
    cudaFuncSetAttribute(gemm_hmma<2, 2, 2>, cudaFuncAttributeMaxDynamicSharedMemorySize, SMEM_DYN);

    // 0) pre-split x and weights to bf16 hi/lo
    split_x_kernel<<<8192, 256>>>(x);
    split_w_kernel<<<180, 256>>>(qkv_w, o1_w, o2_w);

    // 1) QKV projection -> g_qkv [R x 576]
    gemm_hmma<0, 6, 0><<<RR / 128, 256, SMEM_DYN>>>(0, qkv_b, nullptr, nullptr, 576);
    // 2) zero kv accumulators
    zero_kv_kernel<<<24, 1024>>>();
    // 3) LN(k), LN(v) + kv reduction
    ln_kv_kernel<<<dim3(32, 24), 256>>>(klnw, klnb, vlnw, vlnb);
    // 4) attn = q @ kv + x -> split bf16 (g_rh/g_rl)
    attn_kernel<<<dim3(RR / 128, HH), 256>>>(x);
    // 5) h = gelu(ret @ o1_w^T + o1_b) -> split bf16 (g_hh/g_hl)
    gemm_hmma<1, 2, 1><<<RR / 128, 256, SMEM_DYN>>>(576, o1_b, nullptr, nullptr, 192);
    // 6) out = h @ o2_w^T + o2_b + x
    gemm_hmma<2, 2, 2><<<RR / 128, 256, SMEM_DYN>>>(768, o2_b, out, x, 192);
}